// round 1
// baseline (speedup 1.0000x reference)
#include <cuda_runtime.h>
#include <math.h>

#define N_NODES 100000
#define N_EDGES 1600000
#define ET (N_EDGES + N_NODES)
#define NG 5000
#define NH 3

// ---------------- scratch (static device globals; no allocation) ----------------
__device__ float g_bufA[N_NODES * 192];
__device__ float g_bufB[N_NODES * 192];
__device__ float g_as[N_NODES * NH];
__device__ float g_ad[N_NODES * NH];
__device__ float g_emax[N_NODES * NH];
__device__ float g_den[N_NODES * NH];
__device__ float g_pool[NG * 48];
__device__ float g_cnt[NG];

// ---------------- helpers ----------------
__device__ __forceinline__ void atomicMaxF(float* a, float v) {
    int vi = __float_as_int(v);
    if (vi == (int)0x80000000) { vi = 0; v = 0.0f; }  // canonicalize -0.0
    if (v >= 0.0f) atomicMax((int*)a, vi);
    else           atomicMin((unsigned int*)a, (unsigned int)vi);
}

// ---------------- GEMM: Y[M,FOUT] = X[M,K] @ W[K,FOUT] ----------------
// block = (FOUT/4, 8); 32 rows per block; thread computes 4 rows x 4 cols.
template <int K, int FOUT>
__global__ void gemm_kernel(const float* __restrict__ X,
                            const float* __restrict__ W,
                            float* __restrict__ Y) {
    __shared__ float xs[32 * (K + 4)];
    const int row0 = blockIdx.x * 32;
    const int tid = threadIdx.y * blockDim.x + threadIdx.x;
    const int nth = blockDim.x * blockDim.y;
    for (int i = tid; i < 32 * (K / 4); i += nth) {
        int r = i / (K / 4), c = i % (K / 4);
        float4 v = ((const float4*)(X + (size_t)(row0 + r) * K))[c];
        *(float4*)&xs[r * (K + 4) + c * 4] = v;
    }
    __syncthreads();

    const int j = threadIdx.x * 4;
    float acc[4][4];
#pragma unroll
    for (int r = 0; r < 4; ++r)
#pragma unroll
        for (int c = 0; c < 4; ++c) acc[r][c] = 0.0f;

    for (int k = 0; k < K; ++k) {
        float4 w = *(const float4*)(W + (size_t)k * FOUT + j);
#pragma unroll
        for (int r = 0; r < 4; ++r) {
            float xv = xs[(threadIdx.y + r * 8) * (K + 4) + k];
            acc[r][0] += xv * w.x;
            acc[r][1] += xv * w.y;
            acc[r][2] += xv * w.z;
            acc[r][3] += xv * w.w;
        }
    }
#pragma unroll
    for (int r = 0; r < 4; ++r) {
        int row = row0 + threadIdx.y + r * 8;
        *(float4*)(Y + (size_t)row * FOUT + j) =
            make_float4(acc[r][0], acc[r][1], acc[r][2], acc[r][3]);
    }
}

// ---------------- per-node attention coefficients ----------------
template <int C>
__global__ void alpha_kernel(const float* __restrict__ h,
                             const float* __restrict__ a_s,
                             const float* __restrict__ a_d) {
    int idx = blockIdx.x * blockDim.x + threadIdx.x;
    if (idx >= N_NODES * NH) return;
    int n = idx / NH, hh = idx % NH;
    const float* hr = h + (size_t)n * (NH * C) + hh * C;
    const float* asr = a_s + hh * C;
    const float* adr = a_d + hh * C;
    float s = 0.0f, d = 0.0f;
#pragma unroll 8
    for (int c = 0; c < C; ++c) {
        float v = hr[c];
        s += v * asr[c];
        d += v * adr[c];
    }
    g_as[idx] = s;
    g_ad[idx] = d;
}

// ---------------- init per-layer scratch ----------------
template <int FOUT>
__global__ void init_kernel(float* __restrict__ out) {
    int idx = blockIdx.x * blockDim.x + threadIdx.x;
    if (idx < N_NODES * FOUT) out[idx] = 0.0f;
    if (idx < N_NODES * NH) {
        g_emax[idx] = __int_as_float(0xFF800000);  // -inf
        g_den[idx] = 0.0f;
    }
}

// ---------------- edge pass A: segment max ----------------
__global__ void edge_max_kernel(const int* __restrict__ src,
                                const int* __restrict__ dst) {
    int e = blockIdx.x * blockDim.x + threadIdx.x;
    if (e >= ET) return;
    int s = (e < N_EDGES) ? src[e] : (e - N_EDGES);
    int d = (e < N_EDGES) ? dst[e] : (e - N_EDGES);
#pragma unroll
    for (int hh = 0; hh < NH; ++hh) {
        float v = g_as[s * NH + hh] + g_ad[d * NH + hh];
        v = (v > 0.0f) ? v : 0.2f * v;
        atomicMaxF(&g_emax[d * NH + hh], v);
    }
}

// ---------------- edge pass B: unnormalized accumulate + denom ----------------
// warp per edge
template <int C>
__global__ void edge_acc_kernel(const int* __restrict__ src,
                                const int* __restrict__ dst,
                                const float* __restrict__ h,
                                float* __restrict__ out) {
    int gt = blockIdx.x * blockDim.x + threadIdx.x;
    int e = gt >> 5;
    int lane = gt & 31;
    if (e >= ET) return;
    int s = (e < N_EDGES) ? src[e] : (e - N_EDGES);
    int d = (e < N_EDGES) ? dst[e] : (e - N_EDGES);

    float ex[NH];
#pragma unroll
    for (int hh = 0; hh < NH; ++hh) {
        float v = g_as[s * NH + hh] + g_ad[d * NH + hh];
        v = (v > 0.0f) ? v : 0.2f * v;
        ex[hh] = __expf(v - g_emax[d * NH + hh]);
    }
    if (lane < NH) atomicAdd(&g_den[d * NH + lane], ex[lane]);

    const float* hs = h + (size_t)s * (NH * C);
    float* od = out + (size_t)d * (NH * C);
    for (int c = lane; c < NH * C; c += 32) {
        atomicAdd(&od[c], hs[c] * ex[c / C]);
    }
}

// ---------------- finalize: normalize + bias (+ ELU) ----------------
template <int C, bool DO_ELU>
__global__ void final_kernel(float* __restrict__ out, const float* __restrict__ b) {
    int idx = blockIdx.x * blockDim.x + threadIdx.x;
    if (idx >= N_NODES * NH * C) return;
    int j = idx % (NH * C);
    int n = idx / (NH * C);
    int hh = j / C;
    float v = out[idx] / (g_den[n * NH + hh] + 1e-16f) + b[j];
    if (DO_ELU) v = (v > 0.0f) ? v : expm1f(v);
    out[idx] = v;
}

// ---------------- pooling + head ----------------
__global__ void pool_init_kernel(float* __restrict__ loss_slot) {
    int idx = blockIdx.x * blockDim.x + threadIdx.x;
    if (idx < NG * 48) g_pool[idx] = 0.0f;
    if (idx < NG) g_cnt[idx] = 0.0f;
    if (idx == 0 && loss_slot) *loss_slot = 0.0f;
}

__global__ void pool_acc_kernel(const float* __restrict__ h,
                                const int* __restrict__ batch) {
    int idx = blockIdx.x * blockDim.x + threadIdx.x;
    if (idx >= N_NODES * 48) return;
    int n = idx / 48, j = idx % 48;
    atomicAdd(&g_pool[(size_t)batch[n] * 48 + j], h[idx]);
}

__global__ void count_kernel(const int* __restrict__ batch) {
    int n = blockIdx.x * blockDim.x + threadIdx.x;
    if (n >= N_NODES) return;
    atomicAdd(&g_cnt[batch[n]], 1.0f);
}

__global__ void head_kernel(const float* __restrict__ Wl,
                            const float* __restrict__ bl,
                            const float* __restrict__ y,
                            float* __restrict__ outp,
                            float* __restrict__ loss_slot) {
    int g = blockIdx.x * blockDim.x + threadIdx.x;
    if (g >= NG) return;
    float cnt = fmaxf(g_cnt[g], 1.0f);
    float acc = 0.0f;
#pragma unroll
    for (int j = 0; j < 48; ++j) {
        float p = g_pool[g * 48 + j] / cnt;
        p = fmaxf(p, 0.0f);
        acc += p * Wl[j];
    }
    float logit = acc + bl[0];
    outp[g] = 1.0f / (1.0f + expf(-logit));
    if (loss_slot) {
        float sp = fmaxf(logit, 0.0f) + log1pf(expf(-fabsf(logit)));
        atomicAdd(loss_slot, (sp - y[g] * logit) * (1.0f / (float)NG));
    }
}

// ---------------- launch ----------------
static inline int cdiv(int a, int b) { return (a + b - 1) / b; }

extern "C" void kernel_launch(void* const* d_in, const int* in_sizes, int n_in,
                              void* d_out, int out_size) {
    const float* x   = (const float*)d_in[0];
    const float* y   = (const float*)d_in[1];
    const int*   ei  = (const int*)d_in[2];
    const int*   bat = (const int*)d_in[3];
    const float* W1  = (const float*)d_in[4];
    const float* as1 = (const float*)d_in[5];
    const float* ad1 = (const float*)d_in[6];
    const float* b1  = (const float*)d_in[7];
    const float* W2  = (const float*)d_in[8];
    const float* as2 = (const float*)d_in[9];
    const float* ad2 = (const float*)d_in[10];
    const float* b2  = (const float*)d_in[11];
    const float* W3  = (const float*)d_in[12];
    const float* as3 = (const float*)d_in[13];
    const float* ad3 = (const float*)d_in[14];
    const float* b3  = (const float*)d_in[15];
    const float* Wl  = (const float*)d_in[16];
    const float* bl  = (const float*)d_in[17];

    const int* src = ei;
    const int* dst = ei + N_EDGES;

    float* outp = (float*)d_out;
    float* loss_slot = (out_size > NG) ? (outp + NG) : nullptr;

    float *bufA, *bufB;
    cudaGetSymbolAddress((void**)&bufA, g_bufA);
    cudaGetSymbolAddress((void**)&bufB, g_bufB);

    const int TB = 256;

    // ---------- Layer 1: K=128 -> FOUT=192 (C=64), input x, h in A, agg in B ----------
    gemm_kernel<128, 192><<<N_NODES / 32, dim3(48, 8)>>>(x, W1, bufA);
    alpha_kernel<64><<<cdiv(N_NODES * NH, TB), TB>>>(bufA, as1, ad1);
    init_kernel<192><<<cdiv(N_NODES * 192, TB), TB>>>(bufB);
    edge_max_kernel<<<cdiv(ET, TB), TB>>>(src, dst);
    edge_acc_kernel<64><<<cdiv(ET * 32, TB), TB>>>(src, dst, bufA, bufB);
    final_kernel<64, true><<<cdiv(N_NODES * 192, TB), TB>>>(bufB, b1);

    // ---------- Layer 2: K=192 -> FOUT=96 (C=32), input B, h in A, agg in B ----------
    gemm_kernel<192, 96><<<N_NODES / 32, dim3(24, 8)>>>(bufB, W2, bufA);
    alpha_kernel<32><<<cdiv(N_NODES * NH, TB), TB>>>(bufA, as2, ad2);
    init_kernel<96><<<cdiv(N_NODES * 96, TB), TB>>>(bufB);
    edge_max_kernel<<<cdiv(ET, TB), TB>>>(src, dst);
    edge_acc_kernel<32><<<cdiv(ET * 32, TB), TB>>>(src, dst, bufA, bufB);
    final_kernel<32, true><<<cdiv(N_NODES * 96, TB), TB>>>(bufB, b2);

    // ---------- Layer 3: K=96 -> FOUT=48 (C=16), input B, h in A, agg in B ----------
    gemm_kernel<96, 48><<<N_NODES / 32, dim3(12, 8)>>>(bufB, W3, bufA);
    alpha_kernel<16><<<cdiv(N_NODES * NH, TB), TB>>>(bufA, as3, ad3);
    init_kernel<48><<<cdiv(N_NODES * 48, TB), TB>>>(bufB);
    edge_max_kernel<<<cdiv(ET, TB), TB>>>(src, dst);
    edge_acc_kernel<16><<<cdiv(ET * 32, TB), TB>>>(src, dst, bufA, bufB);
    final_kernel<16, false><<<cdiv(N_NODES * 48, TB), TB>>>(bufB, b3);

    // ---------- Pool + head ----------
    pool_init_kernel<<<cdiv(NG * 48, TB), TB>>>(loss_slot);
    pool_acc_kernel<<<cdiv(N_NODES * 48, TB), TB>>>(bufB, bat);
    count_kernel<<<cdiv(N_NODES, TB), TB>>>(bat);
    head_kernel<<<cdiv(NG, 128), 128>>>(Wl, bl, y, outp, loss_slot);
}

// round 2
// speedup vs baseline: 1.6211x; 1.6211x over previous
#include <cuda_runtime.h>
#include <math.h>

#define N_NODES 100000
#define N_EDGES 1600000
#define ET (N_EDGES + N_NODES)
#define NG 5000
#define NH 3
#define NBLK_SCAN ((N_NODES + 1023) / 1024)

// ---------------- scratch (static device globals) ----------------
__device__ float g_bufA[N_NODES * 192];
__device__ float g_bufB[N_NODES * 192];
__device__ float g_as[N_NODES * NH];
__device__ float g_ad[N_NODES * NH];
__device__ int   g_deg[N_NODES];
__device__ int   g_incl[N_NODES];
__device__ int   g_bsum[NBLK_SCAN];
__device__ int   g_start[N_NODES];
__device__ int   g_cur[N_NODES];
__device__ int   g_csr[ET];
__device__ float g_pool[NG * 48];
__device__ float g_cnt[NG];

// ---------------- GEMM: Y[M,FOUT] = X[M,K] @ W[K,FOUT] ----------------
template <int K, int FOUT>
__global__ void gemm_kernel(const float* __restrict__ X,
                            const float* __restrict__ W,
                            float* __restrict__ Y) {
    __shared__ float xs[32 * (K + 4)];
    const int row0 = blockIdx.x * 32;
    const int tid = threadIdx.y * blockDim.x + threadIdx.x;
    const int nth = blockDim.x * blockDim.y;
    for (int i = tid; i < 32 * (K / 4); i += nth) {
        int r = i / (K / 4), c = i % (K / 4);
        float4 v = ((const float4*)(X + (size_t)(row0 + r) * K))[c];
        *(float4*)&xs[r * (K + 4) + c * 4] = v;
    }
    __syncthreads();

    const int j = threadIdx.x * 4;
    float acc[4][4];
#pragma unroll
    for (int r = 0; r < 4; ++r)
#pragma unroll
        for (int c = 0; c < 4; ++c) acc[r][c] = 0.0f;

    for (int k = 0; k < K; ++k) {
        float4 w = *(const float4*)(W + (size_t)k * FOUT + j);
#pragma unroll
        for (int r = 0; r < 4; ++r) {
            float xv = xs[(threadIdx.y + r * 8) * (K + 4) + k];
            acc[r][0] += xv * w.x;
            acc[r][1] += xv * w.y;
            acc[r][2] += xv * w.z;
            acc[r][3] += xv * w.w;
        }
    }
#pragma unroll
    for (int r = 0; r < 4; ++r) {
        int row = row0 + threadIdx.y + r * 8;
        *(float4*)(Y + (size_t)row * FOUT + j) =
            make_float4(acc[r][0], acc[r][1], acc[r][2], acc[r][3]);
    }
}

// ---------------- per-node attention coefficients ----------------
template <int C>
__global__ void alpha_kernel(const float* __restrict__ h,
                             const float* __restrict__ a_s,
                             const float* __restrict__ a_d) {
    int idx = blockIdx.x * blockDim.x + threadIdx.x;
    if (idx >= N_NODES * NH) return;
    int n = idx / NH, hh = idx % NH;
    const float* hr = h + (size_t)n * (NH * C) + hh * C;
    const float* asr = a_s + hh * C;
    const float* adr = a_d + hh * C;
    float s = 0.0f, d = 0.0f;
#pragma unroll 8
    for (int c = 0; c < C; ++c) {
        float v = hr[c];
        s += v * asr[c];
        d += v * adr[c];
    }
    g_as[idx] = s;
    g_ad[idx] = d;
}

// ---------------- CSR build ----------------
__global__ void zero_kernel(float* __restrict__ loss_slot) {
    int i = blockIdx.x * blockDim.x + threadIdx.x;
    if (i < N_NODES) g_deg[i] = 0;
    if (i < NG * 48) g_pool[i] = 0.0f;
    if (i < NG) g_cnt[i] = 0.0f;
    if (i == 0 && loss_slot) *loss_slot = 0.0f;
}

__global__ void hist_kernel(const int* __restrict__ dst) {
    int e = blockIdx.x * blockDim.x + threadIdx.x;
    if (e >= ET) return;
    int d = (e < N_EDGES) ? dst[e] : (e - N_EDGES);
    atomicAdd(&g_deg[d], 1);
}

__global__ void scan1_kernel() {
    __shared__ int sm[1024];
    int i = blockIdx.x * 1024 + threadIdx.x;
    int v = (i < N_NODES) ? g_deg[i] : 0;
    sm[threadIdx.x] = v;
    __syncthreads();
#pragma unroll
    for (int ofs = 1; ofs < 1024; ofs <<= 1) {
        int t = (threadIdx.x >= ofs) ? sm[threadIdx.x - ofs] : 0;
        __syncthreads();
        sm[threadIdx.x] += t;
        __syncthreads();
    }
    if (i < N_NODES) g_incl[i] = sm[threadIdx.x];
    if (threadIdx.x == 1023) g_bsum[blockIdx.x] = sm[1023];
}

__global__ void scan2_kernel() {
    __shared__ int sm[NBLK_SCAN];
    if (threadIdx.x < NBLK_SCAN) sm[threadIdx.x] = g_bsum[threadIdx.x];
    __syncthreads();
    if (threadIdx.x == 0) {
        int run = 0;
        for (int b = 0; b < NBLK_SCAN; ++b) {
            int t = sm[b];
            sm[b] = run;
            run += t;
        }
    }
    __syncthreads();
    if (threadIdx.x < NBLK_SCAN) g_bsum[threadIdx.x] = sm[threadIdx.x];
}

__global__ void scan3_kernel() {
    int i = blockIdx.x * blockDim.x + threadIdx.x;
    if (i >= N_NODES) return;
    int st = g_incl[i] - g_deg[i] + g_bsum[i >> 10];
    g_start[i] = st;
    g_cur[i] = st;
}

__global__ void scatter_kernel(const int* __restrict__ src,
                               const int* __restrict__ dst) {
    int e = blockIdx.x * blockDim.x + threadIdx.x;
    if (e >= ET) return;
    int s = (e < N_EDGES) ? src[e] : (e - N_EDGES);
    int d = (e < N_EDGES) ? dst[e] : (e - N_EDGES);
    int pos = atomicAdd(&g_cur[d], 1);
    g_csr[pos] = s;
}

// ---------------- fused GAT aggregation: warp per dst node ----------------
template <int C, bool DO_ELU>
__global__ void gat_gather_kernel(const float* __restrict__ h,
                                  const float* __restrict__ bias,
                                  float* __restrict__ out) {
    constexpr int FOUT = NH * C;
    constexpr int KK = (FOUT + 31) / 32;
    int warp = (blockIdx.x * blockDim.x + threadIdx.x) >> 5;
    int lane = threadIdx.x & 31;
    if (warp >= N_NODES) return;

    const int start = g_start[warp];
    const int end = start + g_deg[warp];

    float adr[NH];
#pragma unroll
    for (int hh = 0; hh < NH; ++hh) adr[hh] = g_ad[warp * NH + hh];

    // phase 1: max per head
    float mx[NH];
#pragma unroll
    for (int hh = 0; hh < NH; ++hh) mx[hh] = -__int_as_float(0x7F800000);
    for (int e = start + lane; e < end; e += 32) {
        int s = g_csr[e];
#pragma unroll
        for (int hh = 0; hh < NH; ++hh) {
            float v = g_as[s * NH + hh] + adr[hh];
            v = (v > 0.0f) ? v : 0.2f * v;
            mx[hh] = fmaxf(mx[hh], v);
        }
    }
#pragma unroll
    for (int hh = 0; hh < NH; ++hh)
#pragma unroll
        for (int o = 16; o > 0; o >>= 1)
            mx[hh] = fmaxf(mx[hh], __shfl_xor_sync(0xFFFFFFFFu, mx[hh], o));

    // phase 2: sum of exp
    float den[NH] = {0.0f, 0.0f, 0.0f};
    for (int e = start + lane; e < end; e += 32) {
        int s = g_csr[e];
#pragma unroll
        for (int hh = 0; hh < NH; ++hh) {
            float v = g_as[s * NH + hh] + adr[hh];
            v = (v > 0.0f) ? v : 0.2f * v;
            den[hh] += __expf(v - mx[hh]);
        }
    }
#pragma unroll
    for (int hh = 0; hh < NH; ++hh) {
#pragma unroll
        for (int o = 16; o > 0; o >>= 1)
            den[hh] += __shfl_xor_sync(0xFFFFFFFFu, den[hh], o);
        den[hh] = 1.0f / (den[hh] + 1e-16f);
    }

    // phase 3: weighted message accumulation (2-edge unroll for MLP)
    float acc[KK];
#pragma unroll
    for (int k = 0; k < KK; ++k) acc[k] = 0.0f;

    int e = start;
    for (; e + 1 < end; e += 2) {
        int s0 = g_csr[e];
        int s1 = g_csr[e + 1];
        float w0[NH], w1[NH];
#pragma unroll
        for (int hh = 0; hh < NH; ++hh) {
            float v0 = g_as[s0 * NH + hh] + adr[hh];
            float v1 = g_as[s1 * NH + hh] + adr[hh];
            v0 = (v0 > 0.0f) ? v0 : 0.2f * v0;
            v1 = (v1 > 0.0f) ? v1 : 0.2f * v1;
            w0[hh] = __expf(v0 - mx[hh]) * den[hh];
            w1[hh] = __expf(v1 - mx[hh]) * den[hh];
        }
        const float* hs0 = h + (size_t)s0 * FOUT;
        const float* hs1 = h + (size_t)s1 * FOUT;
#pragma unroll
        for (int k = 0; k < KK; ++k) {
            int c = lane + 32 * k;
            if (FOUT % 32 == 0 || c < FOUT) {
                float a = hs0[c];
                float b2 = hs1[c];
                acc[k] += a * w0[c / C] + b2 * w1[c / C];
            }
        }
    }
    if (e < end) {
        int s0 = g_csr[e];
        float w0[NH];
#pragma unroll
        for (int hh = 0; hh < NH; ++hh) {
            float v0 = g_as[s0 * NH + hh] + adr[hh];
            v0 = (v0 > 0.0f) ? v0 : 0.2f * v0;
            w0[hh] = __expf(v0 - mx[hh]) * den[hh];
        }
        const float* hs0 = h + (size_t)s0 * FOUT;
#pragma unroll
        for (int k = 0; k < KK; ++k) {
            int c = lane + 32 * k;
            if (FOUT % 32 == 0 || c < FOUT) acc[k] += hs0[c] * w0[c / C];
        }
    }

    float* od = out + (size_t)warp * FOUT;
#pragma unroll
    for (int k = 0; k < KK; ++k) {
        int c = lane + 32 * k;
        if (FOUT % 32 == 0 || c < FOUT) {
            float v = acc[k] + bias[c];
            if (DO_ELU) v = (v > 0.0f) ? v : expm1f(v);
            od[c] = v;
        }
    }
}

// ---------------- pooling + head ----------------
__global__ void pool_acc_kernel(const float* __restrict__ h,
                                const int* __restrict__ batch) {
    int idx = blockIdx.x * blockDim.x + threadIdx.x;
    if (idx >= N_NODES * 48) return;
    int n = idx / 48, j = idx % 48;
    atomicAdd(&g_pool[(size_t)batch[n] * 48 + j], h[idx]);
}

__global__ void count_kernel(const int* __restrict__ batch) {
    int n = blockIdx.x * blockDim.x + threadIdx.x;
    if (n >= N_NODES) return;
    atomicAdd(&g_cnt[batch[n]], 1.0f);
}

__global__ void head_kernel(const float* __restrict__ Wl,
                            const float* __restrict__ bl,
                            const float* __restrict__ y,
                            float* __restrict__ outp,
                            float* __restrict__ loss_slot) {
    int g = blockIdx.x * blockDim.x + threadIdx.x;
    if (g >= NG) return;
    float cnt = fmaxf(g_cnt[g], 1.0f);
    float acc = 0.0f;
#pragma unroll
    for (int j = 0; j < 48; ++j) {
        float p = g_pool[g * 48 + j] / cnt;
        p = fmaxf(p, 0.0f);
        acc += p * Wl[j];
    }
    float logit = acc + bl[0];
    outp[g] = 1.0f / (1.0f + expf(-logit));
    if (loss_slot) {
        float sp = fmaxf(logit, 0.0f) + log1pf(expf(-fabsf(logit)));
        atomicAdd(loss_slot, (sp - y[g] * logit) * (1.0f / (float)NG));
    }
}

// ---------------- launch ----------------
static inline int cdiv(int a, int b) { return (a + b - 1) / b; }

extern "C" void kernel_launch(void* const* d_in, const int* in_sizes, int n_in,
                              void* d_out, int out_size) {
    const float* x   = (const float*)d_in[0];
    const float* y   = (const float*)d_in[1];
    const int*   ei  = (const int*)d_in[2];
    const int*   bat = (const int*)d_in[3];
    const float* W1  = (const float*)d_in[4];
    const float* as1 = (const float*)d_in[5];
    const float* ad1 = (const float*)d_in[6];
    const float* b1  = (const float*)d_in[7];
    const float* W2  = (const float*)d_in[8];
    const float* as2 = (const float*)d_in[9];
    const float* ad2 = (const float*)d_in[10];
    const float* b2  = (const float*)d_in[11];
    const float* W3  = (const float*)d_in[12];
    const float* as3 = (const float*)d_in[13];
    const float* ad3 = (const float*)d_in[14];
    const float* b3  = (const float*)d_in[15];
    const float* Wl  = (const float*)d_in[16];
    const float* bl  = (const float*)d_in[17];

    const int* src = ei;
    const int* dst = ei + N_EDGES;

    float* outp = (float*)d_out;
    float* loss_slot = (out_size > NG) ? (outp + NG) : nullptr;

    float *bufA, *bufB;
    cudaGetSymbolAddress((void**)&bufA, g_bufA);
    cudaGetSymbolAddress((void**)&bufB, g_bufB);

    const int TB = 256;

    // ---------- CSR build (once; shared by all 3 layers) ----------
    zero_kernel<<<cdiv(NG * 48, TB), TB>>>(loss_slot);
    hist_kernel<<<cdiv(ET, TB), TB>>>(dst);
    scan1_kernel<<<NBLK_SCAN, 1024>>>();
    scan2_kernel<<<1, 128>>>();
    scan3_kernel<<<cdiv(N_NODES, TB), TB>>>();
    scatter_kernel<<<cdiv(ET, TB), TB>>>(src, dst);

    const int GG = cdiv(N_NODES, 8);  // 8 warps per 256-thread block

    // ---------- Layer 1: K=128 -> FOUT=192 (C=64) ----------
    gemm_kernel<128, 192><<<N_NODES / 32, dim3(48, 8)>>>(x, W1, bufA);
    alpha_kernel<64><<<cdiv(N_NODES * NH, TB), TB>>>(bufA, as1, ad1);
    gat_gather_kernel<64, true><<<GG, TB>>>(bufA, b1, bufB);

    // ---------- Layer 2: K=192 -> FOUT=96 (C=32) ----------
    gemm_kernel<192, 96><<<N_NODES / 32, dim3(24, 8)>>>(bufB, W2, bufA);
    alpha_kernel<32><<<cdiv(N_NODES * NH, TB), TB>>>(bufA, as2, ad2);
    gat_gather_kernel<32, true><<<GG, TB>>>(bufA, b2, bufB);

    // ---------- Layer 3: K=96 -> FOUT=48 (C=16) ----------
    gemm_kernel<96, 48><<<N_NODES / 32, dim3(12, 8)>>>(bufB, W3, bufA);
    alpha_kernel<16><<<cdiv(N_NODES * NH, TB), TB>>>(bufA, as3, ad3);
    gat_gather_kernel<16, false><<<GG, TB>>>(bufA, b3, bufB);

    // ---------- Pool + head ----------
    pool_acc_kernel<<<cdiv(N_NODES * 48, TB), TB>>>(bufB, bat);
    count_kernel<<<cdiv(N_NODES, TB), TB>>>(bat);
    head_kernel<<<cdiv(NG, 128), 128>>>(Wl, bl, y, outp, loss_slot);
}